// round 11
// baseline (speedup 1.0000x reference)
#include <cuda_runtime.h>
#include <cuda_fp16.h>
#include <cstdint>

#define NB 4096
#define NS 10
#define CT 320   // conv threads per block

// ===========================================================================
// Device scratch (zero-initialized; padding regions never written => stay 0)
// ===========================================================================
__device__ __align__(16) __half g_h0[NB * 3072];   // feat 2970 + x_train 95, pad->3072
__device__ __align__(16) __half g_h1[NB * 1536];   // 1500 pad 1536
__device__ __align__(16) __half g_h2[NB * 896];    // 800 pad 896
__device__ float g_h3[NB * 100];
// transposed weights (fp16 RN): [Npad][Kpad]
__device__ __align__(16) __half g_w1t[1536 * 3072];
__device__ __align__(16) __half g_w2t[896 * 1536];
__device__ __align__(16) __half g_w3t[128 * 896];

__device__ __forceinline__ uint32_t smem_u32_of(const void* p) {
    uint32_t a;
    asm("{ .reg .u64 t; cvta.to.shared.u64 t, %1; cvt.u32.u64 %0, t; }"
        : "=r"(a) : "l"(p));
    return a;
}

// ---- packed f32x2 helpers -------------------------------------------------
__device__ __forceinline__ unsigned long long pk2(float x, float y) {
    unsigned long long r;
    asm("mov.b64 %0, {%1, %2};" : "=l"(r) : "f"(x), "f"(y));
    return r;
}
__device__ __forceinline__ void upk2(unsigned long long v, float& x, float& y) {
    asm("mov.b64 {%0, %1}, %2;" : "=f"(x), "=f"(y) : "l"(v));
}
#define FMA2(acc, a, b) \
    asm("fma.rn.f32x2 %0, %1, %2, %0;" : "+l"(acc) : "l"(a), "l"(b))

// ===========================================================================
// Conv stack v6: bank-conflict-free layout.
//   Rows [s][c][t], LP = NCH*8+4 (CIN*LP mod 32 in {4,12,20,28} all layers).
//   Item order: ((g*NCH)+tc)*NS + s  -> s innermost => adjacent lanes read
//   different rows on distinct banks.
// ===========================================================================
template <int CIN, int COUT, int CG>
__device__ __forceinline__ void stage_w(const float* __restrict__ cw,
                                        const float* __restrict__ cb,
                                        unsigned long long* Wp,
                                        unsigned long long* Bp, int tid) {
    constexpr int CP = CG / 2;
    constexpr int NG = (COUT + CG - 1) / CG;
    for (int i = tid; i < NS * NG * CIN * 5 * CP; i += CT) {
        int cp = i % CP;
        int t = i / CP;
        int k = t % 5; t /= 5;
        int ci = t % CIN; t /= CIN;
        int g = t % NG;
        int s = t / NG;
        int co0 = g * CG + 2 * cp, co1 = co0 + 1;
        float w0 = (co0 < COUT) ? cw[((s * COUT + co0) * CIN + ci) * 5 + k] : 0.f;
        float w1 = (co1 < COUT) ? cw[((s * COUT + co1) * CIN + ci) * 5 + k] : 0.f;
        Wp[i] = pk2(w0, w1);
    }
    for (int i = tid; i < NS * NG * CP; i += CT) {
        int cp = i % CP;
        int t = i / CP;
        int g = t % NG;
        int s = t / NG;
        int co0 = g * CG + 2 * cp, co1 = co0 + 1;
        float b0 = (co0 < COUT) ? cb[s * COUT + co0] : 0.f;
        float b1 = (co1 < COUT) ? cb[s * COUT + co1] : 0.f;
        Bp[i] = pk2(b0, b1);
    }
}

template <int CIN, int COUT, int CG, int L>
__device__ __forceinline__ void conv_v3(const float* __restrict__ in,
                                        float* __restrict__ out,
                                        const unsigned long long* __restrict__ Wp,
                                        const unsigned long long* __restrict__ Bp,
                                        int tid) {
    constexpr int CP = CG / 2;
    constexpr int NCH = (L + 7) / 8;
    constexpr int LPI = NCH * 8 + 4;   // input rows have same NCH (same L)
    constexpr int LPO = NCH * 8 + 4;
    constexpr int NG = (COUT + CG - 1) / CG;
    constexpr int ITEMS = NS * NG * NCH;
    for (int it = tid; it < ITEMS; it += CT) {
        int s = it % NS;
        int r = it / NS;
        int g = r / NCH;
        int tc = r - g * NCH;
        int t0 = tc * 8;

        unsigned long long acc2[CP][8];
#pragma unroll
        for (int cp = 0; cp < CP; ++cp) {
            unsigned long long bb = Bp[(s * NG + g) * CP + cp];
#pragma unroll
            for (int j = 0; j < 8; ++j) acc2[cp][j] = bb;
        }

        const unsigned long long* wrow = Wp + (size_t)(s * NG + g) * CIN * 5 * CP;
#pragma unroll
        for (int ci = 0; ci < CIN; ++ci) {
            const float* row = in + (s * CIN + ci) * LPI;
            float4 q0 = *(const float4*)(row + t0 - 4);
            float4 q1 = *(const float4*)(row + t0);
            float4 q2 = *(const float4*)(row + t0 + 4);
            float4 q3 = *(const float4*)(row + t0 + 8);
            float win[16] = {q0.x, q0.y, q0.z, q0.w, q1.x, q1.y, q1.z, q1.w,
                             q2.x, q2.y, q2.z, q2.w, q3.x, q3.y, q3.z, q3.w};
            unsigned long long B[13];
#pragma unroll
            for (int m = 0; m < 13; ++m) B[m] = pk2(win[m + 2], win[m + 2]);

#pragma unroll
            for (int cp = 0; cp < CP; ++cp)
#pragma unroll
                for (int k = 0; k < 5; ++k) {
                    unsigned long long wp = wrow[(ci * 5 + k) * CP + cp];
#pragma unroll
                    for (int j = 0; j < 8; ++j)
                        FMA2(acc2[cp][j], B[j + k], wp);
                }
        }

#pragma unroll
        for (int cp = 0; cp < CP; ++cp) {
            int co0 = g * CG + 2 * cp, co1 = co0 + 1;
            float v0[8], v1[8];
#pragma unroll
            for (int j = 0; j < 8; ++j) upk2(acc2[cp][j], v0[j], v1[j]);
#pragma unroll
            for (int j = 0; j < 8; ++j) {
                bool ok = (t0 + j < L);
                v0[j] = ok ? fmaxf(v0[j], 0.f) : 0.f;
                v1[j] = ok ? fmaxf(v1[j], 0.f) : 0.f;
            }
            if (co0 < COUT) {
                float* orow = out + (s * COUT + co0) * LPO;
                *(float4*)(orow + t0) = make_float4(v0[0], v0[1], v0[2], v0[3]);
                *(float4*)(orow + t0 + 4) = make_float4(v0[4], v0[5], v0[6], v0[7]);
                if (tc == NCH - 1)  // zero 4-float tail [NCH*8, LPO)
                    *(float4*)(orow + NCH * 8) = make_float4(0.f, 0.f, 0.f, 0.f);
            }
            if (co1 < COUT) {
                float* orow = out + (s * COUT + co1) * LPO;
                *(float4*)(orow + t0) = make_float4(v1[0], v1[1], v1[2], v1[3]);
                *(float4*)(orow + t0 + 4) = make_float4(v1[4], v1[5], v1[6], v1[7]);
                if (tc == NCH - 1)
                    *(float4*)(orow + NCH * 8) = make_float4(0.f, 0.f, 0.f, 0.f);
            }
        }
    }
}

template <int C, int LIN>
__device__ __forceinline__ void pool_v2(const float* __restrict__ in,
                                        float* __restrict__ out, int tid) {
    constexpr int LOUT = (LIN - 5) / 2 + 1;
    constexpr int LPI = ((LIN + 7) / 8) * 8 + 4;
    constexpr int LPO = ((LOUT + 7) / 8) * 8 + 4;
    constexpr int ITEMS = C * NS * LPO;
    for (int idx = tid; idx < ITEMS; idx += CT) {
        int row = idx / LPO;
        int p = idx - row * LPO;
        float v = 0.f;
        if (p < LOUT) {
            const float* base = in + row * LPI + 2 * p;
            v = fmaxf(fmaxf(fmaxf(base[0], base[1]), fmaxf(base[2], base[3])),
                      base[4]);
        }
        out[row * LPO + p] = v;
    }
}

// LP values: L=237 -> 244, L=117 -> 124, L=57 -> 68.
// bufA holds: L1 out (10*3*244=7320), pool1 (10*5*124=6200), L4 (10*7*124=8680),
//             L5 (10*9*68=6120)                               -> max 8680
// bufB holds: input (10*244=2440), L2 (10*5*244=12200), L3 (10*7*124=8680),
//             pool2 (10*7*68=4760), L6 (10*11*68=7480)        -> max 12200
// smem floats: Wp[5400] | Bp[120] | gA[4] | bufA[8688] | gB[4] | bufB[12208]
#define CONV_SMEM_FLOATS (5400 + 120 + 4 + 8688 + 4 + 12208)

__global__ void __launch_bounds__(CT, 2) conv_kernel(
    const float* __restrict__ meteo, const float* __restrict__ x_train,
    const float* __restrict__ cw1, const float* __restrict__ cb1,
    const float* __restrict__ cw2, const float* __restrict__ cb2,
    const float* __restrict__ cw3, const float* __restrict__ cb3,
    const float* __restrict__ cw4, const float* __restrict__ cb4,
    const float* __restrict__ cw5, const float* __restrict__ cb5,
    const float* __restrict__ cw6, const float* __restrict__ cb6) {
    extern __shared__ float sm[];
    unsigned long long* Wp = (unsigned long long*)sm;
    unsigned long long* Bp = (unsigned long long*)(sm + 5400);
    float* bufA = sm + 5400 + 120 + 4;
    float* bufB = bufA + 8688 + 4;
    int b = blockIdx.x;
    int tid = threadIdx.x;

    if (tid < 4) bufA[-4 + tid] = 0.f;
    else if (tid < 8) bufB[-8 + tid] = 0.f;

    // input transpose: meteo[b][t][s] -> bufB rows [s][t], LP=244, zero pad
    for (int i = tid; i < 10 * 244; i += CT) {
        int s = i / 244, t = i - s * 244;
        bufB[i] = (t < 237) ? meteo[b * 2370 + t * 10 + s] : 0.f;
    }
    stage_w<1, 3, 4>(cw1, cb1, Wp, Bp, tid);
    __syncthreads();
    conv_v3<1, 3, 4, 237>(bufB, bufA, Wp, Bp, tid);
    __syncthreads();

    stage_w<3, 5, 4>(cw2, cb2, Wp, Bp, tid);
    __syncthreads();
    conv_v3<3, 5, 4, 237>(bufA, bufB, Wp, Bp, tid);
    __syncthreads();

    pool_v2<5, 237>(bufB, bufA, tid);  // -> 5 x 117 (LP 124)
    stage_w<5, 7, 4>(cw3, cb3, Wp, Bp, tid);
    __syncthreads();
    conv_v3<5, 7, 4, 117>(bufA, bufB, Wp, Bp, tid);
    __syncthreads();

    stage_w<7, 7, 4>(cw4, cb4, Wp, Bp, tid);
    __syncthreads();
    conv_v3<7, 7, 4, 117>(bufB, bufA, Wp, Bp, tid);
    __syncthreads();

    pool_v2<7, 117>(bufA, bufB, tid);  // -> 7 x 57 (LP 68)
    stage_w<7, 9, 4>(cw5, cb5, Wp, Bp, tid);
    __syncthreads();
    conv_v3<7, 9, 4, 57>(bufB, bufA, Wp, Bp, tid);
    __syncthreads();

    stage_w<9, 11, 4>(cw6, cb6, Wp, Bp, tid);
    __syncthreads();
    conv_v3<9, 11, 4, 57>(bufA, bufB, Wp, Bp, tid);
    __syncthreads();

    // final maxpool (11 x 57 -> 11 x 27) + flatten (co,p,s) -> fp16 h0
    for (int it = tid; it < 11 * 27 * NS; it += CT) {
        int co = it / (27 * NS);
        int r = it - co * (27 * NS);
        int p = r / NS;
        int s = r - p * NS;
        const float* base = &bufB[(s * 11 + co) * 68 + 2 * p];
        float m = fmaxf(fmaxf(fmaxf(base[0], base[1]), fmaxf(base[2], base[3])),
                        base[4]);
        g_h0[(size_t)b * 3072 + it] = __float2half(m);
    }
    for (int i = tid; i < 95; i += CT)
        g_h0[(size_t)b * 3072 + 2970 + i] = __float2half(x_train[b * 95 + i]);
}

// ===========================================================================
// Weight prep: transpose W[K,N] -> T[n][k] fp16 RN (padding stays zero)
// ===========================================================================
__global__ void __launch_bounds__(256) prep_w(const float* __restrict__ W,
                                              int K, int N, int Kpad,
                                              __half* __restrict__ Th) {
    __shared__ float sm[32][33];
    int n0 = blockIdx.x * 32, k0 = blockIdx.y * 32;
    int tx = threadIdx.x, ty = threadIdx.y;  // 32 x 8
    for (int i = ty; i < 32; i += 8) {
        int k = k0 + i, n = n0 + tx;
        sm[i][tx] = (k < K && n < N) ? W[(size_t)k * N + n] : 0.f;
    }
    __syncthreads();
    for (int i = ty; i < 32; i += 8) {
        int n = n0 + i, k = k0 + tx;
        if (n < N && k < K)
            Th[(size_t)n * Kpad + k] = __float2half(sm[tx][i]);
    }
}

// ===========================================================================
// fp16 mma.sync GEMM, single-pass, 4-stage cp.async pipeline (validated r10)
// ===========================================================================
#define RS 80
#define TILE_B (128 * RS)          // 10240
#define STAGE_B (2 * TILE_B)       // 20480: [A|B]
#define NSTAGE 4
#define GEMM_SMEM (NSTAGE * STAGE_B)  // 81920

#define CP_ASYNC(s, g) \
    asm volatile("cp.async.cg.shared.global [%0], [%1], 16;" :: "r"(s), "l"(g) : "memory")
#define CP_COMMIT() asm volatile("cp.async.commit_group;" ::: "memory")
#define CP_WAIT(n)  asm volatile("cp.async.wait_group %0;" :: "n"(n) : "memory")

#define LDMX4(r0, r1, r2, r3, a) \
    asm volatile("ldmatrix.sync.aligned.m8n8.x4.shared.b16 {%0,%1,%2,%3}, [%4];" \
                 : "=r"(r0), "=r"(r1), "=r"(r2), "=r"(r3) : "r"(a))

#define MMAH(c, a, b) \
    asm volatile("mma.sync.aligned.m16n8k16.row.col.f32.f16.f16.f32 " \
                 "{%0,%1,%2,%3}, {%4,%5,%6,%7}, {%8,%9}, {%0,%1,%2,%3};" \
                 : "+f"((c)[0]), "+f"((c)[1]), "+f"((c)[2]), "+f"((c)[3]) \
                 : "r"((a)[0]), "r"((a)[1]), "r"((a)[2]), "r"((a)[3]), \
                   "r"((b)[0]), "r"((b)[1]))

template <bool OUT_HALF>
__global__ void __launch_bounds__(256, 2) mma_gemm(
    const __half* __restrict__ A, const __half* __restrict__ B,
    const float* __restrict__ bias, int N, int Kpad,
    __half* __restrict__ C, float* __restrict__ Cf, int ldc) {
    extern __shared__ __align__(16) char smem[];
    uint32_t su = smem_u32_of(smem);

    int tid = threadIdx.x, wid = tid >> 5, lane = tid & 31;
    int warp_m = wid & 1, warp_n = wid >> 1;
    int m0 = blockIdx.y * 128, n0 = blockIdx.x * 128;
    int nkb = Kpad >> 5;

    const __half* gsrc[2] = {A + (size_t)m0 * Kpad, B + (size_t)n0 * Kpad};
    int c0 = tid * 2, c1 = tid * 2 + 1;
    int r0c = c0 >> 2, f0 = (c0 & 3) * 8;
    int r1c = c1 >> 2, f1 = (c1 & 3) * 8;

    auto load_stage = [&](int slot, int kbe) {
        uint32_t sb = su + slot * STAGE_B;
#pragma unroll
        for (int t = 0; t < 2; ++t) {
            const __half* g = gsrc[t];
            uint32_t tb = sb + t * TILE_B;
            CP_ASYNC(tb + r0c * RS + f0 * 2, g + (size_t)r0c * Kpad + kbe + f0);
            CP_ASYNC(tb + r1c * RS + f1 * 2, g + (size_t)r1c * Kpad + kbe + f1);
        }
        CP_COMMIT();
    };

    int g = lane >> 3, lr = lane & 7;
    uint32_t a_off = (uint32_t)((warp_m * 64 + (g & 1) * 8 + lr) * RS + (g >> 1) * 16);
    uint32_t b_off = (uint32_t)((warp_n * 32 + (g >> 1) * 8 + lr) * RS + (g & 1) * 16);

    float acc[4][4][4];
#pragma unroll
    for (int i = 0; i < 4; i++)
#pragma unroll
        for (int j = 0; j < 4; j++)
#pragma unroll
            for (int e = 0; e < 4; e++) acc[i][j][e] = 0.f;

    load_stage(0, 0);
    load_stage(1, 32);
    load_stage(2, 64);

    for (int kb = 0; kb < nkb; ++kb) {
        CP_WAIT(2);
        __syncthreads();
        if (kb + 3 < nkb) load_stage((kb + 3) & 3, (kb + 3) * 32);

        uint32_t sb = su + (kb & 3) * STAGE_B;
#pragma unroll
        for (int ks = 0; ks < 2; ++ks) {
            uint32_t ko = ks * 32;
            uint32_t ar[4][4], br[4][2];
#pragma unroll
            for (int i = 0; i < 4; ++i) {
                uint32_t ad = sb + a_off + ko + i * (16 * RS);
                LDMX4(ar[i][0], ar[i][1], ar[i][2], ar[i][3], ad);
            }
#pragma unroll
            for (int j = 0; j < 4; j += 2) {
                uint32_t bd = sb + TILE_B + b_off + ko + j * (8 * RS);
                LDMX4(br[j][0], br[j][1], br[j + 1][0], br[j + 1][1], bd);
            }
#pragma unroll
            for (int i = 0; i < 4; ++i)
#pragma unroll
                for (int j = 0; j < 4; ++j)
                    MMAH(acc[i][j], ar[i], br[j]);
        }
    }

    __syncthreads();
    int row_b = m0 + warp_m * 64 + (lane >> 2);
    int col_b = n0 + warp_n * 32 + (lane & 3) * 2;
#pragma unroll
    for (int i = 0; i < 4; ++i)
#pragma unroll
        for (int j = 0; j < 4; ++j) {
            int col = col_b + j * 8;
            if (col < N) {
                float bv0 = bias[col], bv1 = bias[col + 1];
                int r_lo = row_b + i * 16, r_hi = r_lo + 8;
                float v00 = fmaxf(acc[i][j][0] + bv0, 0.f);
                float v01 = fmaxf(acc[i][j][1] + bv1, 0.f);
                float v10 = fmaxf(acc[i][j][2] + bv0, 0.f);
                float v11 = fmaxf(acc[i][j][3] + bv1, 0.f);
                if (OUT_HALF) {
                    *(__half2*)&C[(size_t)r_lo * ldc + col] =
                        __halves2half2(__float2half(v00), __float2half(v01));
                    *(__half2*)&C[(size_t)r_hi * ldc + col] =
                        __halves2half2(__float2half(v10), __float2half(v11));
                } else {
                    Cf[(size_t)r_lo * ldc + col] = v00;
                    Cf[(size_t)r_lo * ldc + col + 1] = v01;
                    Cf[(size_t)r_hi * ldc + col] = v10;
                    Cf[(size_t)r_hi * ldc + col + 1] = v11;
                }
            }
        }
}

// ===========================================================================
// Tail: h4 = relu(h3 @ W4 + b4); out = [h4, xg] @ Wc + bc
// ===========================================================================
__global__ void __launch_bounds__(256) tail_kernel(
    const float* __restrict__ h3, const float* __restrict__ W4,
    const float* __restrict__ b4, const float* __restrict__ xg,
    const float* __restrict__ Wc, const float* __restrict__ bc,
    float* __restrict__ out) {
    __shared__ float w4s[2000];
    __shared__ float b4s[20], wcs[21], bcs[1];
    int tid = threadIdx.x;
    for (int i = tid; i < 2000; i += 256) w4s[i] = W4[i];
    if (tid < 20) b4s[tid] = b4[tid];
    if (tid < 21) wcs[tid] = Wc[tid];
    if (tid == 0) bcs[0] = bc[0];
    __syncthreads();

    int b = blockIdx.x * 256 + tid;
    float acc[20];
#pragma unroll
    for (int j = 0; j < 20; ++j) acc[j] = b4s[j];
    const float* hr = h3 + (size_t)b * 100;
    for (int k = 0; k < 100; ++k) {
        float a = hr[k];
        const float* w = &w4s[k * 20];
#pragma unroll
        for (int j = 0; j < 20; ++j) acc[j] = fmaf(a, w[j], acc[j]);
    }
    float o = bcs[0] + xg[b] * wcs[20];
#pragma unroll
    for (int j = 0; j < 20; ++j) o += fmaxf(acc[j], 0.f) * wcs[j];
    out[b] = o;
}

// ===========================================================================
extern "C" void kernel_launch(void* const* d_in, const int* in_sizes, int n_in,
                              void* d_out, int out_size) {
    const float* x_train = (const float*)d_in[0];
    const float* meteo = (const float*)d_in[1];
    const float* xg = (const float*)d_in[2];
    const float* cw[6];
    const float* cb[6];
    for (int l = 0; l < 6; l++) {
        cw[l] = (const float*)d_in[3 + 2 * l];
        cb[l] = (const float*)d_in[4 + 2 * l];
    }
    const float* W1 = (const float*)d_in[15];
    const float* b1 = (const float*)d_in[16];
    const float* W2 = (const float*)d_in[17];
    const float* b2 = (const float*)d_in[18];
    const float* W3 = (const float*)d_in[19];
    const float* b3 = (const float*)d_in[20];
    const float* W4 = (const float*)d_in[21];
    const float* b4 = (const float*)d_in[22];
    const float* Wc = (const float*)d_in[23];
    const float* bc = (const float*)d_in[24];

    __half *h0, *h1, *h2;
    __half *w1t, *w2t, *w3t;
    float* h3;
    cudaGetSymbolAddress((void**)&h0, g_h0);
    cudaGetSymbolAddress((void**)&h1, g_h1);
    cudaGetSymbolAddress((void**)&h2, g_h2);
    cudaGetSymbolAddress((void**)&w1t, g_w1t);
    cudaGetSymbolAddress((void**)&w2t, g_w2t);
    cudaGetSymbolAddress((void**)&w3t, g_w3t);
    cudaGetSymbolAddress((void**)&h3, g_h3);

    const int conv_smem = CONV_SMEM_FLOATS * (int)sizeof(float);
    cudaFuncSetAttribute(conv_kernel, cudaFuncAttributeMaxDynamicSharedMemorySize,
                         conv_smem);
    cudaFuncSetAttribute(mma_gemm<true>,
                         cudaFuncAttributeMaxDynamicSharedMemorySize, GEMM_SMEM);
    cudaFuncSetAttribute(mma_gemm<false>,
                         cudaFuncAttributeMaxDynamicSharedMemorySize, GEMM_SMEM);

    prep_w<<<dim3(47, 96), dim3(32, 8)>>>(W1, 3065, 1500, 3072, w1t);
    prep_w<<<dim3(25, 47), dim3(32, 8)>>>(W2, 1500, 800, 1536, w2t);
    prep_w<<<dim3(4, 25), dim3(32, 8)>>>(W3, 800, 100, 896, w3t);

    conv_kernel<<<NB, CT, conv_smem>>>(meteo, x_train, cw[0], cb[0], cw[1], cb[1],
                                       cw[2], cb[2], cw[3], cb[3], cw[4], cb[4],
                                       cw[5], cb[5]);

    // L1: 4096 x 1500, Kpad = 3072
    mma_gemm<true><<<dim3(12, 32), 256, GEMM_SMEM>>>(
        h0, w1t, b1, 1500, 3072, h1, nullptr, 1536);
    // L2: 4096 x 800, Kpad = 1536
    mma_gemm<true><<<dim3(7, 32), 256, GEMM_SMEM>>>(
        h1, w2t, b2, 800, 1536, h2, nullptr, 896);
    // L3: 4096 x 100, Kpad = 896
    mma_gemm<false><<<dim3(1, 32), 256, GEMM_SMEM>>>(
        h2, w3t, b3, 100, 896, nullptr, h3, 100);

    tail_kernel<<<16, 256>>>(h3, W4, b4, xg, Wc, bc, (float*)d_out);
}

// round 12
// speedup vs baseline: 1.0204x; 1.0204x over previous
#include <cuda_runtime.h>
#include <cuda_fp16.h>
#include <cstdint>
#include <cstring>

#define NB 4096
#define NS 10
#define CT 320   // conv threads per block

// ===========================================================================
// Device scratch (zero-initialized; padding regions never written => stay 0)
// ===========================================================================
__device__ __align__(16) __half g_h0[NB * 3072];   // feat 2970 + x_train 95, pad->3072
__device__ __align__(16) __half g_h1[NB * 1536];   // 1500 pad 1536
__device__ __align__(16) __half g_h2[NB * 896];    // 800 pad 896
__device__ float g_h3[NB * 100];
// transposed weights (fp16 RN): [Npad][Kpad]
__device__ __align__(16) __half g_w1t[1536 * 3072];
__device__ __align__(16) __half g_w2t[896 * 1536];
__device__ __align__(16) __half g_w3t[128 * 896];

__device__ __forceinline__ uint32_t smem_u32_of(const void* p) {
    uint32_t a;
    asm("{ .reg .u64 t; cvta.to.shared.u64 t, %1; cvt.u32.u64 %0, t; }"
        : "=r"(a) : "l"(p));
    return a;
}

// ---- packed f32x2 helpers -------------------------------------------------
__device__ __forceinline__ unsigned long long pk2(float x, float y) {
    unsigned long long r;
    asm("mov.b64 %0, {%1, %2};" : "=l"(r) : "f"(x), "f"(y));
    return r;
}
__device__ __forceinline__ void upk2(unsigned long long v, float& x, float& y) {
    asm("mov.b64 {%0, %1}, %2;" : "=f"(x), "=f"(y) : "l"(v));
}
#define FMA2(acc, a, b) \
    asm("fma.rn.f32x2 %0, %1, %2, %0;" : "+l"(acc) : "l"(a), "l"(b))

// ===========================================================================
// Conv stack v7: fp16 activations in smem (3 CTAs/SM), channel-pair f32x2.
//   Row layout per (s, c): LPH = NCH*8+24 halves; data at [8, 8+L);
//   [0,8) front guard and [8+NCH*8, 8+NCH*8+8) tail guard are zero.
//   Item = (tc*NG + g)*NS + s  (s innermost -> window loads broadcast/spread).
// ===========================================================================
template <int CIN, int COUT>
__device__ __forceinline__ void stage_w(const float* __restrict__ cw,
                                        const float* __restrict__ cb,
                                        unsigned long long* Wp,
                                        unsigned long long* Bp, int tid) {
    constexpr int NG = (COUT + 1) / 2;
    for (int i = tid; i < NS * NG * CIN * 5; i += CT) {
        int k = i % 5;
        int t = i / 5;
        int ci = t % CIN; t /= CIN;
        int g = t % NG;
        int s = t / NG;
        int co0 = 2 * g, co1 = co0 + 1;
        float w0 = cw[((s * COUT + co0) * CIN + ci) * 5 + k];
        float w1 = (co1 < COUT) ? cw[((s * COUT + co1) * CIN + ci) * 5 + k] : 0.f;
        Wp[i] = pk2(w0, w1);
    }
    for (int i = tid; i < NS * NG; i += CT) {
        int g = i % NG, s = i / NG;
        int co0 = 2 * g, co1 = co0 + 1;
        float b0 = cb[s * COUT + co0];
        float b1 = (co1 < COUT) ? cb[s * COUT + co1] : 0.f;
        Bp[i] = pk2(b0, b1);
    }
}

template <int CIN, int COUT, int L>
__device__ __forceinline__ void conv_h(const __half* __restrict__ in,
                                       __half* __restrict__ out,
                                       const unsigned long long* __restrict__ Wp,
                                       const unsigned long long* __restrict__ Bp,
                                       int tid) {
    constexpr int NCH = (L + 7) / 8;
    constexpr int LPH = NCH * 8 + 24;
    constexpr int NG = (COUT + 1) / 2;
    constexpr int ITEMS = NS * NG * NCH;
    for (int it = tid; it < ITEMS; it += CT) {
        int s = it % NS;
        int q = it / NS;
        int g = q % NG;
        int tc = q / NG;
        int t0 = tc * 8;

        unsigned long long acc[8];
        unsigned long long bb = Bp[s * NG + g];
#pragma unroll
        for (int t = 0; t < 8; ++t) acc[t] = bb;

        const unsigned long long* wrow = Wp + (size_t)(s * NG + g) * CIN * 5;
#pragma unroll
        for (int ci = 0; ci < CIN; ++ci) {
            const __half* row = in + (s * CIN + ci) * LPH;
            // 24 halves covering absolute t = [t0-8, t0+16)
            uint4 ra = *(const uint4*)(row + t0);
            uint4 rb = *(const uint4*)(row + t0 + 8);
            uint4 rc = *(const uint4*)(row + t0 + 16);
            __align__(16) __half hh[24];
            *(uint4*)(hh + 0) = ra;
            *(uint4*)(hh + 8) = rb;
            *(uint4*)(hh + 16) = rc;

            unsigned long long wp[5];
#pragma unroll
            for (int k = 0; k < 5; ++k) wp[k] = wrow[ci * 5 + k];

            // block 1: t = 0..3, window f-index u = t+k in [0,8): halves hh[6..13]
            {
                unsigned long long W1[8];
#pragma unroll
                for (int u = 0; u < 8; ++u) {
                    float f = __half2float(hh[6 + u]);
                    W1[u] = pk2(f, f);
                }
#pragma unroll
                for (int k = 0; k < 5; ++k)
#pragma unroll
                    for (int t = 0; t < 4; ++t)
                        FMA2(acc[t], W1[t + k], wp[k]);
            }
            // block 2: t = 4..7, u' = (t-4)+k in [0,8): halves hh[10..17]
            {
                unsigned long long W2[8];
#pragma unroll
                for (int u = 0; u < 8; ++u) {
                    float f = __half2float(hh[10 + u]);
                    W2[u] = pk2(f, f);
                }
#pragma unroll
                for (int k = 0; k < 5; ++k)
#pragma unroll
                    for (int t = 0; t < 4; ++t)
                        FMA2(acc[4 + t], W2[t + k], wp[k]);
            }
        }

        int co0 = 2 * g, co1 = co0 + 1;
        float x[8], y[8];
#pragma unroll
        for (int t = 0; t < 8; ++t) upk2(acc[t], x[t], y[t]);
#pragma unroll
        for (int t = 0; t < 8; ++t) {
            bool ok = (t0 + t < L);
            x[t] = ok ? fmaxf(x[t], 0.f) : 0.f;
            y[t] = ok ? fmaxf(y[t], 0.f) : 0.f;
        }
        const uint4 z16 = {0u, 0u, 0u, 0u};
        {
            __align__(16) __half2 hx[4];
#pragma unroll
            for (int i = 0; i < 4; ++i)
                hx[i] = __floats2half2_rn(x[2 * i], x[2 * i + 1]);
            __half* orow = out + (s * COUT + co0) * LPH;
            *(uint4*)(orow + 8 + t0) = *(const uint4*)hx;
            if (tc == 0) *(uint4*)(orow) = z16;
            if (tc == NCH - 1) *(uint4*)(orow + 8 + NCH * 8) = z16;
        }
        if (co1 < COUT) {
            __align__(16) __half2 hy[4];
#pragma unroll
            for (int i = 0; i < 4; ++i)
                hy[i] = __floats2half2_rn(y[2 * i], y[2 * i + 1]);
            __half* orow = out + (s * COUT + co1) * LPH;
            *(uint4*)(orow + 8 + t0) = *(const uint4*)hy;
            if (tc == 0) *(uint4*)(orow) = z16;
            if (tc == NCH - 1) *(uint4*)(orow + 8 + NCH * 8) = z16;
        }
    }
}

template <int C, int LIN>
__device__ __forceinline__ void pool_h(const __half* __restrict__ in,
                                       __half* __restrict__ out, int tid) {
    constexpr int LOUT = (LIN - 5) / 2 + 1;
    constexpr int LPI = ((LIN + 7) / 8) * 8 + 24;
    constexpr int LPO = ((LOUT + 7) / 8) * 8 + 24;
    constexpr int ITEMS = C * NS * LPO;
    for (int idx = tid; idx < ITEMS; idx += CT) {
        int row = idx / LPO;
        int qq = idx - row * LPO;
        float v = 0.f;
        if (qq >= 8 && qq < 8 + LOUT) {
            const __half* base = in + row * LPI + 8 + 2 * (qq - 8);
            v = fmaxf(fmaxf(fmaxf(__half2float(base[0]), __half2float(base[1])),
                            fmaxf(__half2float(base[2]), __half2float(base[3]))),
                      __half2float(base[4]));
        }
        out[row * LPO + qq] = __float2half(v);
    }
}

// smem bytes: Wp 2700 ull (21600) | Bp 60 ull (480) | bufA 10080 h (20160)
//           | bufB 13200 h (26400)   => 68640 B/CTA, 3 CTAs/SM
#define CONV_SMEM_BYTES (21600 + 480 + 20160 + 26400)

__global__ void __launch_bounds__(CT, 3) conv_kernel(
    const float* __restrict__ meteo, const float* __restrict__ x_train,
    const float* __restrict__ cw1, const float* __restrict__ cb1,
    const float* __restrict__ cw2, const float* __restrict__ cb2,
    const float* __restrict__ cw3, const float* __restrict__ cb3,
    const float* __restrict__ cw4, const float* __restrict__ cb4,
    const float* __restrict__ cw5, const float* __restrict__ cb5,
    const float* __restrict__ cw6, const float* __restrict__ cb6) {
    extern __shared__ __align__(16) char smc[];
    unsigned long long* Wp = (unsigned long long*)smc;
    unsigned long long* Bp = (unsigned long long*)(smc + 21600);
    __half* bufA = (__half*)(smc + 22080);
    __half* bufB = (__half*)(smc + 42240);
    int b = blockIdx.x;
    int tid = threadIdx.x;

    // input transpose: meteo[b][t][s] -> bufB rows [s], LPH(237)=264, guards 0
    for (int i = tid; i < 10 * 264; i += CT) {
        int s = i / 264, qq = i - s * 264;
        float v = (qq >= 8 && qq < 8 + 237) ? meteo[b * 2370 + (qq - 8) * 10 + s]
                                            : 0.f;
        bufB[i] = __float2half(v);
    }
    stage_w<1, 3>(cw1, cb1, Wp, Bp, tid);
    __syncthreads();
    conv_h<1, 3, 237>(bufB, bufA, Wp, Bp, tid);    // ITEMS=600
    __syncthreads();

    stage_w<3, 5>(cw2, cb2, Wp, Bp, tid);
    __syncthreads();
    conv_h<3, 5, 237>(bufA, bufB, Wp, Bp, tid);    // ITEMS=900
    __syncthreads();

    pool_h<5, 237>(bufB, bufA, tid);               // -> 5 x 117 (LPH 144)
    stage_w<5, 7>(cw3, cb3, Wp, Bp, tid);
    __syncthreads();
    conv_h<5, 7, 117>(bufA, bufB, Wp, Bp, tid);    // ITEMS=600
    __syncthreads();

    stage_w<7, 7>(cw4, cb4, Wp, Bp, tid);
    __syncthreads();
    conv_h<7, 7, 117>(bufB, bufA, Wp, Bp, tid);    // ITEMS=600
    __syncthreads();

    pool_h<7, 117>(bufA, bufB, tid);               // -> 7 x 57 (LPH 88)
    stage_w<7, 9>(cw5, cb5, Wp, Bp, tid);
    __syncthreads();
    conv_h<7, 9, 57>(bufB, bufA, Wp, Bp, tid);     // ITEMS=400
    __syncthreads();

    stage_w<9, 11>(cw6, cb6, Wp, Bp, tid);
    __syncthreads();
    conv_h<9, 11, 57>(bufA, bufB, Wp, Bp, tid);    // ITEMS=480
    __syncthreads();

    // final maxpool (11 x 57 -> 11 x 27) + flatten (co,p,s) -> fp16 h0
    for (int it = tid; it < 11 * 27 * NS; it += CT) {
        int co = it / (27 * NS);
        int r = it - co * (27 * NS);
        int p = r / NS;
        int s = r - p * NS;
        const __half* base = &bufB[(s * 11 + co) * 88 + 8 + 2 * p];
        float m = fmaxf(fmaxf(fmaxf(__half2float(base[0]), __half2float(base[1])),
                              fmaxf(__half2float(base[2]), __half2float(base[3]))),
                        __half2float(base[4]));
        g_h0[(size_t)b * 3072 + it] = __float2half(m);
    }
    for (int i = tid; i < 95; i += CT)
        g_h0[(size_t)b * 3072 + 2970 + i] = __float2half(x_train[b * 95 + i]);
}

// ===========================================================================
// Weight prep: transpose W[K,N] -> T[n][k] fp16 RN (padding stays zero)
// ===========================================================================
__global__ void __launch_bounds__(256) prep_w(const float* __restrict__ W,
                                              int K, int N, int Kpad,
                                              __half* __restrict__ Th) {
    __shared__ float sm[32][33];
    int n0 = blockIdx.x * 32, k0 = blockIdx.y * 32;
    int tx = threadIdx.x, ty = threadIdx.y;  // 32 x 8
    for (int i = ty; i < 32; i += 8) {
        int k = k0 + i, n = n0 + tx;
        sm[i][tx] = (k < K && n < N) ? W[(size_t)k * N + n] : 0.f;
    }
    __syncthreads();
    for (int i = ty; i < 32; i += 8) {
        int n = n0 + i, k = k0 + tx;
        if (n < N && k < K)
            Th[(size_t)n * Kpad + k] = __float2half(sm[tx][i]);
    }
}

// ===========================================================================
// fp16 mma.sync GEMM, single-pass, 4-stage cp.async pipeline (validated r10)
// ===========================================================================
#define RS 80
#define TILE_B (128 * RS)          // 10240
#define STAGE_B (2 * TILE_B)       // 20480: [A|B]
#define NSTAGE 4
#define GEMM_SMEM (NSTAGE * STAGE_B)  // 81920

#define CP_ASYNC(s, g) \
    asm volatile("cp.async.cg.shared.global [%0], [%1], 16;" :: "r"(s), "l"(g) : "memory")
#define CP_COMMIT() asm volatile("cp.async.commit_group;" ::: "memory")
#define CP_WAIT(n)  asm volatile("cp.async.wait_group %0;" :: "n"(n) : "memory")

#define LDMX4(r0, r1, r2, r3, a) \
    asm volatile("ldmatrix.sync.aligned.m8n8.x4.shared.b16 {%0,%1,%2,%3}, [%4];" \
                 : "=r"(r0), "=r"(r1), "=r"(r2), "=r"(r3) : "r"(a))

#define MMAH(c, a, b) \
    asm volatile("mma.sync.aligned.m16n8k16.row.col.f32.f16.f16.f32 " \
                 "{%0,%1,%2,%3}, {%4,%5,%6,%7}, {%8,%9}, {%0,%1,%2,%3};" \
                 : "+f"((c)[0]), "+f"((c)[1]), "+f"((c)[2]), "+f"((c)[3]) \
                 : "r"((a)[0]), "r"((a)[1]), "r"((a)[2]), "r"((a)[3]), \
                   "r"((b)[0]), "r"((b)[1]))

template <bool OUT_HALF>
__global__ void __launch_bounds__(256, 2) mma_gemm(
    const __half* __restrict__ A, const __half* __restrict__ B,
    const float* __restrict__ bias, int N, int Kpad,
    __half* __restrict__ C, float* __restrict__ Cf, int ldc) {
    extern __shared__ __align__(16) char smem[];
    uint32_t su = smem_u32_of(smem);

    int tid = threadIdx.x, wid = tid >> 5, lane = tid & 31;
    int warp_m = wid & 1, warp_n = wid >> 1;
    int m0 = blockIdx.y * 128, n0 = blockIdx.x * 128;
    int nkb = Kpad >> 5;

    const __half* gsrc[2] = {A + (size_t)m0 * Kpad, B + (size_t)n0 * Kpad};
    int c0 = tid * 2, c1 = tid * 2 + 1;
    int r0c = c0 >> 2, f0 = (c0 & 3) * 8;
    int r1c = c1 >> 2, f1 = (c1 & 3) * 8;

    auto load_stage = [&](int slot, int kbe) {
        uint32_t sb = su + slot * STAGE_B;
#pragma unroll
        for (int t = 0; t < 2; ++t) {
            const __half* g = gsrc[t];
            uint32_t tb = sb + t * TILE_B;
            CP_ASYNC(tb + r0c * RS + f0 * 2, g + (size_t)r0c * Kpad + kbe + f0);
            CP_ASYNC(tb + r1c * RS + f1 * 2, g + (size_t)r1c * Kpad + kbe + f1);
        }
        CP_COMMIT();
    };

    int g = lane >> 3, lr = lane & 7;
    uint32_t a_off = (uint32_t)((warp_m * 64 + (g & 1) * 8 + lr) * RS + (g >> 1) * 16);
    uint32_t b_off = (uint32_t)((warp_n * 32 + (g >> 1) * 8 + lr) * RS + (g & 1) * 16);

    float acc[4][4][4];
#pragma unroll
    for (int i = 0; i < 4; i++)
#pragma unroll
        for (int j = 0; j < 4; j++)
#pragma unroll
            for (int e = 0; e < 4; e++) acc[i][j][e] = 0.f;

    load_stage(0, 0);
    load_stage(1, 32);
    load_stage(2, 64);

    for (int kb = 0; kb < nkb; ++kb) {
        CP_WAIT(2);
        __syncthreads();
        if (kb + 3 < nkb) load_stage((kb + 3) & 3, (kb + 3) * 32);

        uint32_t sb = su + (kb & 3) * STAGE_B;
#pragma unroll
        for (int ks = 0; ks < 2; ++ks) {
            uint32_t ko = ks * 32;
            uint32_t ar[4][4], br[4][2];
#pragma unroll
            for (int i = 0; i < 4; ++i) {
                uint32_t ad = sb + a_off + ko + i * (16 * RS);
                LDMX4(ar[i][0], ar[i][1], ar[i][2], ar[i][3], ad);
            }
#pragma unroll
            for (int j = 0; j < 4; j += 2) {
                uint32_t bd = sb + TILE_B + b_off + ko + j * (8 * RS);
                LDMX4(br[j][0], br[j][1], br[j + 1][0], br[j + 1][1], bd);
            }
#pragma unroll
            for (int i = 0; i < 4; ++i)
#pragma unroll
                for (int j = 0; j < 4; ++j)
                    MMAH(acc[i][j], ar[i], br[j]);
        }
    }

    __syncthreads();
    int row_b = m0 + warp_m * 64 + (lane >> 2);
    int col_b = n0 + warp_n * 32 + (lane & 3) * 2;
#pragma unroll
    for (int i = 0; i < 4; ++i)
#pragma unroll
        for (int j = 0; j < 4; ++j) {
            int col = col_b + j * 8;
            if (col < N) {
                float bv0 = bias[col], bv1 = bias[col + 1];
                int r_lo = row_b + i * 16, r_hi = r_lo + 8;
                float v00 = fmaxf(acc[i][j][0] + bv0, 0.f);
                float v01 = fmaxf(acc[i][j][1] + bv1, 0.f);
                float v10 = fmaxf(acc[i][j][2] + bv0, 0.f);
                float v11 = fmaxf(acc[i][j][3] + bv1, 0.f);
                if (OUT_HALF) {
                    *(__half2*)&C[(size_t)r_lo * ldc + col] =
                        __halves2half2(__float2half(v00), __float2half(v01));
                    *(__half2*)&C[(size_t)r_hi * ldc + col] =
                        __halves2half2(__float2half(v10), __float2half(v11));
                } else {
                    Cf[(size_t)r_lo * ldc + col] = v00;
                    Cf[(size_t)r_lo * ldc + col + 1] = v01;
                    Cf[(size_t)r_hi * ldc + col] = v10;
                    Cf[(size_t)r_hi * ldc + col + 1] = v11;
                }
            }
        }
}

// ===========================================================================
// Tail: h4 = relu(h3 @ W4 + b4); out = [h4, xg] @ Wc + bc
// ===========================================================================
__global__ void __launch_bounds__(256) tail_kernel(
    const float* __restrict__ h3, const float* __restrict__ W4,
    const float* __restrict__ b4, const float* __restrict__ xg,
    const float* __restrict__ Wc, const float* __restrict__ bc,
    float* __restrict__ out) {
    __shared__ float w4s[2000];
    __shared__ float b4s[20], wcs[21], bcs[1];
    int tid = threadIdx.x;
    for (int i = tid; i < 2000; i += 256) w4s[i] = W4[i];
    if (tid < 20) b4s[tid] = b4[tid];
    if (tid < 21) wcs[tid] = Wc[tid];
    if (tid == 0) bcs[0] = bc[0];
    __syncthreads();

    int b = blockIdx.x * 256 + tid;
    float acc[20];
#pragma unroll
    for (int j = 0; j < 20; ++j) acc[j] = b4s[j];
    const float* hr = h3 + (size_t)b * 100;
    for (int k = 0; k < 100; ++k) {
        float a = hr[k];
        const float* w = &w4s[k * 20];
#pragma unroll
        for (int j = 0; j < 20; ++j) acc[j] = fmaf(a, w[j], acc[j]);
    }
    float o = bcs[0] + xg[b] * wcs[20];
#pragma unroll
    for (int j = 0; j < 20; ++j) o += fmaxf(acc[j], 0.f) * wcs[j];
    out[b] = o;
}

// ===========================================================================
extern "C" void kernel_launch(void* const* d_in, const int* in_sizes, int n_in,
                              void* d_out, int out_size) {
    const float* x_train = (const float*)d_in[0];
    const float* meteo = (const float*)d_in[1];
    const float* xg = (const float*)d_in[2];
    const float* cw[6];
    const float* cb[6];
    for (int l = 0; l < 6; l++) {
        cw[l] = (const float*)d_in[3 + 2 * l];
        cb[l] = (const float*)d_in[4 + 2 * l];
    }
    const float* W1 = (const float*)d_in[15];
    const float* b1 = (const float*)d_in[16];
    const float* W2 = (const float*)d_in[17];
    const float* b2 = (const float*)d_in[18];
    const float* W3 = (const float*)d_in[19];
    const float* b3 = (const float*)d_in[20];
    const float* W4 = (const float*)d_in[21];
    const float* b4 = (const float*)d_in[22];
    const float* Wc = (const float*)d_in[23];
    const float* bc = (const float*)d_in[24];

    __half *h0, *h1, *h2;
    __half *w1t, *w2t, *w3t;
    float* h3;
    cudaGetSymbolAddress((void**)&h0, g_h0);
    cudaGetSymbolAddress((void**)&h1, g_h1);
    cudaGetSymbolAddress((void**)&h2, g_h2);
    cudaGetSymbolAddress((void**)&w1t, g_w1t);
    cudaGetSymbolAddress((void**)&w2t, g_w2t);
    cudaGetSymbolAddress((void**)&w3t, g_w3t);
    cudaGetSymbolAddress((void**)&h3, g_h3);

    cudaFuncSetAttribute(conv_kernel, cudaFuncAttributeMaxDynamicSharedMemorySize,
                         CONV_SMEM_BYTES);
    cudaFuncSetAttribute(mma_gemm<true>,
                         cudaFuncAttributeMaxDynamicSharedMemorySize, GEMM_SMEM);
    cudaFuncSetAttribute(mma_gemm<false>,
                         cudaFuncAttributeMaxDynamicSharedMemorySize, GEMM_SMEM);

    prep_w<<<dim3(47, 96), dim3(32, 8)>>>(W1, 3065, 1500, 3072, w1t);
    prep_w<<<dim3(25, 47), dim3(32, 8)>>>(W2, 1500, 800, 1536, w2t);
    prep_w<<<dim3(4, 25), dim3(32, 8)>>>(W3, 800, 100, 896, w3t);

    conv_kernel<<<NB, CT, CONV_SMEM_BYTES>>>(meteo, x_train, cw[0], cb[0],
                                             cw[1], cb[1], cw[2], cb[2],
                                             cw[3], cb[3], cw[4], cb[4],
                                             cw[5], cb[5]);

    // L1: 4096 x 1500, Kpad = 3072
    mma_gemm<true><<<dim3(12, 32), 256, GEMM_SMEM>>>(
        h0, w1t, b1, 1500, 3072, h1, nullptr, 1536);
    // L2: 4096 x 800, Kpad = 1536
    mma_gemm<true><<<dim3(7, 32), 256, GEMM_SMEM>>>(
        h1, w2t, b2, 800, 1536, h2, nullptr, 896);
    // L3: 4096 x 100, Kpad = 896
    mma_gemm<false><<<dim3(1, 32), 256, GEMM_SMEM>>>(
        h2, w3t, b3, 100, 896, nullptr, h3, 100);

    tail_kernel<<<16, 256>>>(h3, W4, b4, xg, Wc, bc, (float*)d_out);
}